// round 1
// baseline (speedup 1.0000x reference)
#include <cuda_runtime.h>
#include <cuda_bf16.h>
#include <math.h>

#define NN   20000
#define NE   160000
#define HID  128
#define HEADS 8
#define HC   1024
#define LAYERS 6

// ---------------- scratch (device globals; no allocation allowed) ----------
static __device__ float g_h  [NN * HID];
static __device__ float g_hn [NN * HID];
static __device__ float g_q  [NN * HC];
static __device__ float g_k  [NN * HC];
static __device__ float g_v  [NN * HC];
static __device__ float g_xr [NN * HC];
static __device__ float g_out[NN * HC];
static __device__ float g_ex [NE * HEADS];
static __device__ float g_amax [NN * HEADS];
static __device__ float g_denom[NN * HEADS];

// ---------------- helpers ---------------------------------------------------
__device__ __forceinline__ void atomicMaxF(float* addr, float value) {
    if (value >= 0.0f)
        atomicMax((int*)addr, __float_as_int(value));
    else
        atomicMin((unsigned int*)addr, __float_as_uint(value));
}

__device__ __forceinline__ float block_reduce_sum(float v, float* red) {
    int t = threadIdx.x;
    #pragma unroll
    for (int o = 16; o; o >>= 1) v += __shfl_xor_sync(0xffffffffu, v, o);
    if ((t & 31) == 0) red[t >> 5] = v;
    __syncthreads();
    if (t < 8) {
        v = red[t];
        #pragma unroll
        for (int o = 4; o; o >>= 1) v += __shfl_xor_sync(0xffu, v, o);
        if (t == 0) red[0] = v;
    }
    __syncthreads();
    float r = red[0];
    __syncthreads();
    return r;
}

// ---------------- input projection: h = x @ Win + b_in ----------------------
__global__ void inproj_kernel(const float* __restrict__ x,
                              const float* __restrict__ Win,
                              const float* __restrict__ b_in,
                              float* __restrict__ h) {
    int n = blockIdx.x;
    int j = threadIdx.x;   // 0..127
    __shared__ float sx[15];
    if (j < 15) sx[j] = x[n * 15 + j];
    __syncthreads();
    float acc = b_in[j];
    #pragma unroll
    for (int k = 0; k < 15; k++) acc += sx[k] * Win[k * HID + j];
    h[n * HID + j] = acc;
}

// ---------------- reset: out = 0, amax = -inf, denom = 0 --------------------
__global__ void reset_kernel() {
    size_t i = (size_t)blockIdx.x * blockDim.x + threadIdx.x;
    float4 z = make_float4(0.f, 0.f, 0.f, 0.f);
    if (i < (size_t)NN * HC / 4) ((float4*)g_out)[i] = z;
    if (i < (size_t)NN * HEADS) {
        g_amax[i]  = __int_as_float(0xff800000);  // -inf
        g_denom[i] = 0.f;
    }
}

// ---------------- tiled fp32 GEMM: C = A[M,K]@W[K,N] + bias -----------------
// epilogue==1: C = relu(C + resid)   (resid is [M,N])
#define GBM 64
#define GBN 64
#define GBK 16

__global__ __launch_bounds__(256) void gemm64_kernel(
        const float* __restrict__ A, const float* __restrict__ W,
        const float* __restrict__ bias, const float* __restrict__ resid,
        float* __restrict__ C, int M, int K, int N, int epilogue) {
    __shared__ float As[GBK][GBM];   // transposed A tile
    __shared__ float Bs[GBK][GBN];

    int tid = threadIdx.x;
    int tx = tid & 15;   // n dir
    int ty = tid >> 4;   // m dir
    int m0 = blockIdx.y * GBM;
    int n0 = blockIdx.x * GBN;

    int arow = tid >> 2;           // 0..63
    int acol = (tid & 3) * 4;      // 0,4,8,12
    int brow = tid >> 4;           // 0..15
    int bcol = (tid & 15) * 4;     // 0..60

    int am = m0 + arow;
    bool avalid = am < M;

    float acc[4][4] = {};

    for (int k0 = 0; k0 < K; k0 += GBK) {
        float4 a4 = avalid ? *(const float4*)(A + (size_t)am * K + k0 + acol)
                           : make_float4(0.f, 0.f, 0.f, 0.f);
        As[acol + 0][arow] = a4.x;
        As[acol + 1][arow] = a4.y;
        As[acol + 2][arow] = a4.z;
        As[acol + 3][arow] = a4.w;
        *(float4*)&Bs[brow][bcol] =
            *(const float4*)(W + (size_t)(k0 + brow) * N + n0 + bcol);
        __syncthreads();
        #pragma unroll
        for (int kk = 0; kk < GBK; kk++) {
            float4 ra = *(const float4*)&As[kk][ty * 4];
            float4 rb = *(const float4*)&Bs[kk][tx * 4];
            float a_[4] = {ra.x, ra.y, ra.z, ra.w};
            float b_[4] = {rb.x, rb.y, rb.z, rb.w};
            #pragma unroll
            for (int i = 0; i < 4; i++)
                #pragma unroll
                for (int j = 0; j < 4; j++)
                    acc[i][j] = fmaf(a_[i], b_[j], acc[i][j]);
        }
        __syncthreads();
    }

    #pragma unroll
    for (int i = 0; i < 4; i++) {
        int m = m0 + ty * 4 + i;
        if (m >= M) continue;
        #pragma unroll
        for (int j = 0; j < 4; j++) {
            int n = n0 + tx * 4 + j;
            float v = acc[i][j] + bias[n];
            if (epilogue) {
                v += resid[(size_t)m * N + n];
                v = fmaxf(v, 0.f);
            }
            C[(size_t)m * N + n] = v;
        }
    }
}

// ---------------- per-edge attention logits ---------------------------------
// block = 256 threads = 8 warps; warp w handles head w of edge blockIdx.x
__global__ __launch_bounds__(256) void logits_kernel(const int* __restrict__ ei) {
    int e = blockIdx.x;
    int src = ei[e];
    int dst = ei[NE + e];
    int h    = threadIdx.x >> 5;
    int lane = threadIdx.x & 31;
    const float4* q = (const float4*)(g_q + (size_t)dst * HC + h * HID);
    const float4* k = (const float4*)(g_k + (size_t)src * HC + h * HID);
    float4 a = q[lane], b = k[lane];
    float d = a.x * b.x + a.y * b.y + a.z * b.z + a.w * b.w;
    #pragma unroll
    for (int o = 16; o; o >>= 1) d += __shfl_xor_sync(0xffffffffu, d, o);
    if (lane == 0) {
        float alpha = d * 0.08838834764831845f;  // 1/sqrt(128)
        g_ex[(size_t)e * HEADS + h] = alpha;
        atomicMaxF(&g_amax[(size_t)dst * HEADS + h], alpha);
    }
}

// ---------------- exp + segment-sum denominator ------------------------------
__global__ void expdenom_kernel(const int* __restrict__ ei) {
    int idx = blockIdx.x * blockDim.x + threadIdx.x;
    if (idx >= NE * HEADS) return;
    int e = idx >> 3, h = idx & 7;
    int dst = ei[NE + e];
    float ex = expf(g_ex[idx] - g_amax[(size_t)dst * HEADS + h]);
    g_ex[idx] = ex;
    atomicAdd(&g_denom[(size_t)dst * HEADS + h], ex);
}

// ---------------- weighted message scatter-sum -------------------------------
__global__ __launch_bounds__(256) void scatter_kernel(const int* __restrict__ ei) {
    int e = blockIdx.x;
    int src = ei[e];
    int dst = ei[NE + e];
    __shared__ float s_a[HEADS];
    if (threadIdx.x < HEADS)
        s_a[threadIdx.x] = g_ex[(size_t)e * HEADS + threadIdx.x] /
                           (g_denom[(size_t)dst * HEADS + threadIdx.x] + 1e-16f);
    __syncthreads();
    int c = threadIdx.x * 4;           // 0..1020, head = c>>7 uniform per warp
    float a = s_a[c >> 7];
    float4 v = *(const float4*)(g_v + (size_t)src * HC + c);
    float* o = g_out + (size_t)dst * HC + c;
    atomicAdd(o + 0, v.x * a);
    atomicAdd(o + 1, v.y * a);
    atomicAdd(o + 2, v.z * a);
    atomicAdd(o + 3, v.w * a);
}

// ---------------- beta gate + LayerNorm --------------------------------------
// one block (256 threads) per node; reads g_out (agg) + g_xr, writes g_out
__global__ __launch_bounds__(256) void beta_ln_kernel(
        const float* __restrict__ Wb, const float* __restrict__ lng,
        const float* __restrict__ lnb) {
    int n = blockIdx.x;
    __shared__ float s_o[HC];
    __shared__ float s_x[HC];
    __shared__ float red[8];
    const float* o  = g_out + (size_t)n * HC;
    const float* xr = g_xr  + (size_t)n * HC;

    float acc = 0.f;
    for (int i = threadIdx.x; i < HC; i += 256) {
        float a = o[i], b = xr[i];
        s_o[i] = a; s_x[i] = b;
        acc += a * Wb[i] + b * Wb[HC + i] + (a - b) * Wb[2 * HC + i];
    }
    __syncthreads();
    float tot = block_reduce_sum(acc, red);
    float beta = 1.f / (1.f + expf(-tot));

    float ls = 0.f;
    for (int i = threadIdx.x; i < HC; i += 256) {
        float g = beta * s_x[i] + (1.f - beta) * s_o[i];
        s_o[i] = g;
        ls += g;
    }
    __syncthreads();
    float mu = block_reduce_sum(ls, red) * (1.f / HC);

    float lv = 0.f;
    for (int i = threadIdx.x; i < HC; i += 256) {
        float d = s_o[i] - mu;
        lv += d * d;
    }
    float var = block_reduce_sum(lv, red) * (1.f / HC);
    float rstd = rsqrtf(var + 1e-5f);

    float* dst = g_out + (size_t)n * HC;
    for (int i = threadIdx.x; i < HC; i += 256)
        dst[i] = (s_o[i] - mu) * rstd * lng[i] + lnb[i];
}

// ---------------- launch -----------------------------------------------------
extern "C" void kernel_launch(void* const* d_in, const int* in_sizes, int n_in,
                              void* d_out, int out_size) {
    const float* x    = (const float*)d_in[0];
    const int*   ei   = (const int*)  d_in[1];
    const float* Win  = (const float*)d_in[2];
    const float* b_in = (const float*)d_in[3];
    const float* Wq   = (const float*)d_in[4];
    const float* bq   = (const float*)d_in[5];
    const float* Wk   = (const float*)d_in[6];
    const float* bk   = (const float*)d_in[7];
    const float* Wv   = (const float*)d_in[8];
    const float* bv   = (const float*)d_in[9];
    const float* Ws   = (const float*)d_in[10];
    const float* bs   = (const float*)d_in[11];
    const float* Wb   = (const float*)d_in[12];
    const float* lng  = (const float*)d_in[13];
    const float* lnb  = (const float*)d_in[14];
    const float* Wp   = (const float*)d_in[15];
    const float* bp   = (const float*)d_in[16];
    float* out = (float*)d_out;

    float *g_h_p, *g_hn_p, *g_q_p, *g_k_p, *g_v_p, *g_xr_p, *g_out_p;
    cudaGetSymbolAddress((void**)&g_h_p,  g_h);
    cudaGetSymbolAddress((void**)&g_hn_p, g_hn);
    cudaGetSymbolAddress((void**)&g_q_p,  g_q);
    cudaGetSymbolAddress((void**)&g_k_p,  g_k);
    cudaGetSymbolAddress((void**)&g_v_p,  g_v);
    cudaGetSymbolAddress((void**)&g_xr_p, g_xr);
    cudaGetSymbolAddress((void**)&g_out_p, g_out);

    inproj_kernel<<<NN, 128>>>(x, Win, b_in, g_h_p);

    float* h  = g_h_p;
    float* hn = g_hn_p;
    dim3 blk(256);
    dim3 grid_qkvs(HC / GBN, (NN + GBM - 1) / GBM);   // 16 x 313
    dim3 grid_proj(HID / GBN, (NN + GBM - 1) / GBM);  //  2 x 313

    for (int l = 0; l < LAYERS; l++) {
        reset_kernel<<<(NN * HC / 4 + 255) / 256, 256>>>();

        const float* wq = Wq + (size_t)l * HID * HC;
        const float* wk = Wk + (size_t)l * HID * HC;
        const float* wv = Wv + (size_t)l * HID * HC;
        const float* ws = Ws + (size_t)l * HID * HC;
        gemm64_kernel<<<grid_qkvs, blk>>>(h, wq, bq + l * HC, nullptr, g_q_p,  NN, HID, HC, 0);
        gemm64_kernel<<<grid_qkvs, blk>>>(h, wk, bk + l * HC, nullptr, g_k_p,  NN, HID, HC, 0);
        gemm64_kernel<<<grid_qkvs, blk>>>(h, wv, bv + l * HC, nullptr, g_v_p,  NN, HID, HC, 0);
        gemm64_kernel<<<grid_qkvs, blk>>>(h, ws, bs + l * HC, nullptr, g_xr_p, NN, HID, HC, 0);

        logits_kernel<<<NE, 256>>>(ei);
        expdenom_kernel<<<(NE * HEADS + 255) / 256, 256>>>(ei);
        scatter_kernel<<<NE, 256>>>(ei);

        beta_ln_kernel<<<NN, 256>>>(Wb + (size_t)l * 3 * HC,
                                    lng + (size_t)l * HC, lnb + (size_t)l * HC);

        float* dst = (l == LAYERS - 1) ? out : hn;
        gemm64_kernel<<<grid_proj, blk>>>(g_out_p, Wp + (size_t)l * HC * HID,
                                          bp + (size_t)l * HID, h, dst,
                                          NN, HC, HID, 1);
        if (l < LAYERS - 1) { float* t = h; h = hn; hn = t; }
    }
}

// round 2
// speedup vs baseline: 1.6128x; 1.6128x over previous
#include <cuda_runtime.h>
#include <cuda_bf16.h>
#include <math.h>

#define NN   20000
#define NE   160000
#define HID  128
#define HEADS 8
#define HC   1024
#define LAYERS 6

// ---------------- scratch (device globals; no allocation allowed) ----------
static __device__ float g_h  [NN * HID];
static __device__ float g_hn [NN * HID];
static __device__ float g_q  [NN * HC];
static __device__ float g_k  [NN * HC];
static __device__ float g_v  [NN * HC];
static __device__ float g_xr [NN * HC];
static __device__ float g_out[NN * HC];
// CSR
static __device__ int g_deg   [NN];
static __device__ int g_rowptr[NN + 1];
static __device__ int g_cur   [NN];
static __device__ int g_esrc  [NE];

// ---------------- input projection: h = x @ Win + b_in ----------------------
__global__ void inproj_kernel(const float* __restrict__ x,
                              const float* __restrict__ Win,
                              const float* __restrict__ b_in,
                              float* __restrict__ h) {
    int n = blockIdx.x;
    int j = threadIdx.x;   // 0..127
    __shared__ float sx[15];
    if (j < 15) sx[j] = x[n * 15 + j];
    __syncthreads();
    float acc = b_in[j];
    #pragma unroll
    for (int k = 0; k < 15; k++) acc += sx[k] * Win[k * HID + j];
    h[n * HID + j] = acc;
}

// ---------------- CSR build --------------------------------------------------
__global__ void csr_zero() {
    int i = blockIdx.x * blockDim.x + threadIdx.x;
    if (i < NN) g_deg[i] = 0;
}
__global__ void csr_count(const int* __restrict__ ei) {
    int e = blockIdx.x * blockDim.x + threadIdx.x;
    if (e < NE) atomicAdd(&g_deg[ei[NE + e]], 1);
}
__global__ __launch_bounds__(1024) void csr_scan() {
    __shared__ int wsum[32], wofs[32], s_tot;
    int t = threadIdx.x, lane = t & 31, w = t >> 5;
    int base = 0;
    for (int i0 = 0; i0 < NN; i0 += 1024) {
        int i = i0 + t;
        int v = (i < NN) ? g_deg[i] : 0;
        int s = v;
        #pragma unroll
        for (int o = 1; o < 32; o <<= 1) {
            int u = __shfl_up_sync(0xffffffffu, s, o);
            if (lane >= o) s += u;
        }
        if (lane == 31) wsum[w] = s;
        __syncthreads();
        if (w == 0) {
            int a = wsum[lane];
            int ss = a;
            #pragma unroll
            for (int o = 1; o < 32; o <<= 1) {
                int u = __shfl_up_sync(0xffffffffu, ss, o);
                if (lane >= o) ss += u;
            }
            wofs[lane] = ss - a;
            if (lane == 31) s_tot = ss;
        }
        __syncthreads();
        int excl = base + wofs[w] + (s - v);
        if (i < NN) { g_rowptr[i] = excl; g_cur[i] = excl; }
        base += s_tot;
        __syncthreads();
    }
    if (t == 0) g_rowptr[NN] = base;
}
__global__ void csr_fill(const int* __restrict__ ei) {
    int e = blockIdx.x * blockDim.x + threadIdx.x;
    if (e < NE) {
        int dst = ei[NE + e];
        int pos = atomicAdd(&g_cur[dst], 1);
        g_esrc[pos] = ei[e];
    }
}

// ---------------- fused QKVS GEMM: 128x128 tile, 8x8 micro ------------------
// computes C{0..3} = A @ W{0..3} + b{0..3}, W: [128,1024], A: [M,128]
__global__ __launch_bounds__(256, 2) void gemm_qkvs(
        const float* __restrict__ A,
        const float* __restrict__ W0, const float* __restrict__ W1,
        const float* __restrict__ W2, const float* __restrict__ W3,
        const float* __restrict__ b0, const float* __restrict__ b1,
        const float* __restrict__ b2, const float* __restrict__ b3,
        float* __restrict__ C0, float* __restrict__ C1,
        float* __restrict__ C2, float* __restrict__ C3, int M) {
    __shared__ float As[2][16][128];
    __shared__ float Bs[2][16][128];

    int tid = threadIdx.x;
    int wsel = blockIdx.x >> 3;
    int n0   = (blockIdx.x & 7) * 128;
    const float* W    = wsel == 0 ? W0 : wsel == 1 ? W1 : wsel == 2 ? W2 : W3;
    const float* bias = wsel == 0 ? b0 : wsel == 1 ? b1 : wsel == 2 ? b2 : b3;
    float*       C    = wsel == 0 ? C0 : wsel == 1 ? C1 : wsel == 2 ? C2 : C3;

    int m0 = blockIdx.y * 128;
    int tx = tid & 15, ty = tid >> 4;

    int arow = tid >> 1;
    int acol = (tid & 1) * 8;
    int am   = m0 + arow;
    bool av  = am < M;
    int brow = tid >> 4;
    int bcol = (tid & 15) * 8;

    const float4 z4 = make_float4(0.f, 0.f, 0.f, 0.f);
    // prologue: chunk 0
    {
        float4 a0 = av ? *(const float4*)(A + (size_t)am * 128 + acol)     : z4;
        float4 a1 = av ? *(const float4*)(A + (size_t)am * 128 + acol + 4) : z4;
        As[0][acol+0][arow]=a0.x; As[0][acol+1][arow]=a0.y; As[0][acol+2][arow]=a0.z; As[0][acol+3][arow]=a0.w;
        As[0][acol+4][arow]=a1.x; As[0][acol+5][arow]=a1.y; As[0][acol+6][arow]=a1.z; As[0][acol+7][arow]=a1.w;
        *(float4*)&Bs[0][brow][bcol]     = *(const float4*)(W + (size_t)brow * HC + n0 + bcol);
        *(float4*)&Bs[0][brow][bcol + 4] = *(const float4*)(W + (size_t)brow * HC + n0 + bcol + 4);
    }
    __syncthreads();

    float acc[8][8] = {};
    #pragma unroll
    for (int c = 0; c < 8; c++) {          // 8 chunks of K=16
        int buf = c & 1;
        float4 na0, na1, nb0, nb1;
        bool more = c < 7;
        if (more) {
            int k0 = (c + 1) * 16;
            na0 = av ? *(const float4*)(A + (size_t)am * 128 + k0 + acol)     : z4;
            na1 = av ? *(const float4*)(A + (size_t)am * 128 + k0 + acol + 4) : z4;
            nb0 = *(const float4*)(W + (size_t)(k0 + brow) * HC + n0 + bcol);
            nb1 = *(const float4*)(W + (size_t)(k0 + brow) * HC + n0 + bcol + 4);
        }
        #pragma unroll
        for (int kk = 0; kk < 16; kk++) {
            float4 ra0 = *(const float4*)&As[buf][kk][ty * 8];
            float4 ra1 = *(const float4*)&As[buf][kk][ty * 8 + 4];
            float4 rb0 = *(const float4*)&Bs[buf][kk][tx * 8];
            float4 rb1 = *(const float4*)&Bs[buf][kk][tx * 8 + 4];
            float a_[8] = {ra0.x, ra0.y, ra0.z, ra0.w, ra1.x, ra1.y, ra1.z, ra1.w};
            float b_[8] = {rb0.x, rb0.y, rb0.z, rb0.w, rb1.x, rb1.y, rb1.z, rb1.w};
            #pragma unroll
            for (int i = 0; i < 8; i++)
                #pragma unroll
                for (int j = 0; j < 8; j++)
                    acc[i][j] = fmaf(a_[i], b_[j], acc[i][j]);
        }
        if (more) {
            int nb = buf ^ 1;
            As[nb][acol+0][arow]=na0.x; As[nb][acol+1][arow]=na0.y; As[nb][acol+2][arow]=na0.z; As[nb][acol+3][arow]=na0.w;
            As[nb][acol+4][arow]=na1.x; As[nb][acol+5][arow]=na1.y; As[nb][acol+6][arow]=na1.z; As[nb][acol+7][arow]=na1.w;
            *(float4*)&Bs[nb][brow][bcol]     = nb0;
            *(float4*)&Bs[nb][brow][bcol + 4] = nb1;
        }
        __syncthreads();
    }

    float4 bi0 = *(const float4*)(bias + n0 + tx * 8);
    float4 bi1 = *(const float4*)(bias + n0 + tx * 8 + 4);
    #pragma unroll
    for (int i = 0; i < 8; i++) {
        int m = m0 + ty * 8 + i;
        if (m >= M) continue;
        float4 o0 = make_float4(acc[i][0]+bi0.x, acc[i][1]+bi0.y, acc[i][2]+bi0.z, acc[i][3]+bi0.w);
        float4 o1 = make_float4(acc[i][4]+bi1.x, acc[i][5]+bi1.y, acc[i][6]+bi1.z, acc[i][7]+bi1.w);
        *(float4*)(C + (size_t)m * HC + n0 + tx * 8)     = o0;
        *(float4*)(C + (size_t)m * HC + n0 + tx * 8 + 4) = o1;
    }
}

// ---------------- proj GEMM: [M,1024]@[1024,128], 128x64 tile, 8x4 micro ----
// epilogue: C = relu(acc + bias + resid)
__global__ __launch_bounds__(256) void gemm_proj(
        const float* __restrict__ A, const float* __restrict__ W,
        const float* __restrict__ bias, const float* __restrict__ resid,
        float* __restrict__ C, int M) {
    __shared__ float As[2][16][128];
    __shared__ float Bs[2][16][64];

    int tid = threadIdx.x;
    int n0 = blockIdx.x * 64;
    int m0 = blockIdx.y * 128;
    int tx = tid & 15, ty = tid >> 4;

    int arow = tid >> 1;
    int acol = (tid & 1) * 8;
    int am   = m0 + arow;
    bool av  = am < M;
    int brow = tid >> 4;
    int bcol = (tid & 15) * 4;

    const float4 z4 = make_float4(0.f, 0.f, 0.f, 0.f);
    {
        float4 a0 = av ? *(const float4*)(A + (size_t)am * HC + acol)     : z4;
        float4 a1 = av ? *(const float4*)(A + (size_t)am * HC + acol + 4) : z4;
        As[0][acol+0][arow]=a0.x; As[0][acol+1][arow]=a0.y; As[0][acol+2][arow]=a0.z; As[0][acol+3][arow]=a0.w;
        As[0][acol+4][arow]=a1.x; As[0][acol+5][arow]=a1.y; As[0][acol+6][arow]=a1.z; As[0][acol+7][arow]=a1.w;
        *(float4*)&Bs[0][brow][bcol] = *(const float4*)(W + (size_t)brow * HID + n0 + bcol);
    }
    __syncthreads();

    float acc[8][4] = {};
    for (int c = 0; c < 64; c++) {
        int buf = c & 1;
        float4 na0, na1, nb0;
        bool more = c < 63;
        if (more) {
            int k0 = (c + 1) * 16;
            na0 = av ? *(const float4*)(A + (size_t)am * HC + k0 + acol)     : z4;
            na1 = av ? *(const float4*)(A + (size_t)am * HC + k0 + acol + 4) : z4;
            nb0 = *(const float4*)(W + (size_t)(k0 + brow) * HID + n0 + bcol);
        }
        #pragma unroll
        for (int kk = 0; kk < 16; kk++) {
            float4 ra0 = *(const float4*)&As[buf][kk][ty * 8];
            float4 ra1 = *(const float4*)&As[buf][kk][ty * 8 + 4];
            float4 rb0 = *(const float4*)&Bs[buf][kk][tx * 4];
            float a_[8] = {ra0.x, ra0.y, ra0.z, ra0.w, ra1.x, ra1.y, ra1.z, ra1.w};
            float b_[4] = {rb0.x, rb0.y, rb0.z, rb0.w};
            #pragma unroll
            for (int i = 0; i < 8; i++)
                #pragma unroll
                for (int j = 0; j < 4; j++)
                    acc[i][j] = fmaf(a_[i], b_[j], acc[i][j]);
        }
        if (more) {
            int nb = buf ^ 1;
            As[nb][acol+0][arow]=na0.x; As[nb][acol+1][arow]=na0.y; As[nb][acol+2][arow]=na0.z; As[nb][acol+3][arow]=na0.w;
            As[nb][acol+4][arow]=na1.x; As[nb][acol+5][arow]=na1.y; As[nb][acol+6][arow]=na1.z; As[nb][acol+7][arow]=na1.w;
            *(float4*)&Bs[nb][brow][bcol] = nb0;
        }
        __syncthreads();
    }

    float4 bi = *(const float4*)(bias + n0 + tx * 4);
    #pragma unroll
    for (int i = 0; i < 8; i++) {
        int m = m0 + ty * 8 + i;
        if (m >= M) continue;
        float4 r = *(const float4*)(resid + (size_t)m * HID + n0 + tx * 4);
        float4 o;
        o.x = fmaxf(acc[i][0] + bi.x + r.x, 0.f);
        o.y = fmaxf(acc[i][1] + bi.y + r.y, 0.f);
        o.z = fmaxf(acc[i][2] + bi.z + r.z, 0.f);
        o.w = fmaxf(acc[i][3] + bi.w + r.w, 0.f);
        *(float4*)(C + (size_t)m * HID + n0 + tx * 4) = o;
    }
}

// ---------------- fused attention + beta gate + LayerNorm -------------------
// one block (128 threads) per destination node.
// thread t: head h = t>>4, owns elements [h*128 + (t&15)*8 .. +8)
__device__ __forceinline__ float breduce128(float v, float* red) {
    #pragma unroll
    for (int o = 16; o; o >>= 1) v += __shfl_xor_sync(0xffffffffu, v, o);
    if ((threadIdx.x & 31) == 0) red[threadIdx.x >> 5] = v;
    __syncthreads();
    float r = red[0] + red[1] + red[2] + red[3];
    __syncthreads();
    return r;
}

__global__ __launch_bounds__(128) void attn_fused(
        const float* __restrict__ Wb, const float* __restrict__ lng,
        const float* __restrict__ lnb) {
    int n = blockIdx.x;
    int t = threadIdx.x;
    int off = (t >> 4) * 128 + (t & 15) * 8;
    __shared__ float red[4];

    const float4* qp = (const float4*)(g_q + (size_t)n * HC + off);
    float4 q0 = qp[0], q1 = qp[1];

    float acc[8] = {0.f,0.f,0.f,0.f,0.f,0.f,0.f,0.f};
    float m = -__int_as_float(0x7f800000) * 0.f - __int_as_float(0x7f800000); // -inf
    m = __int_as_float(0xff800000);
    float d = 0.f;

    int beg = g_rowptr[n], end = g_rowptr[n + 1];
    for (int p = beg; p < end; p++) {
        int src = g_esrc[p];
        const float4* kp = (const float4*)(g_k + (size_t)src * HC + off);
        const float4* vp = (const float4*)(g_v + (size_t)src * HC + off);
        float4 k0 = kp[0], k1 = kp[1];
        float4 v0 = vp[0], v1 = vp[1];
        float dot = q0.x*k0.x + q0.y*k0.y + q0.z*k0.z + q0.w*k0.w
                  + q1.x*k1.x + q1.y*k1.y + q1.z*k1.z + q1.w*k1.w;
        #pragma unroll
        for (int o = 8; o; o >>= 1) dot += __shfl_xor_sync(0xffffffffu, dot, o);
        float alpha = dot * 0.08838834764831845f;   // 1/sqrt(128)
        float mn = fmaxf(m, alpha);
        float sc = expf(m - mn);
        float pw = expf(alpha - mn);
        d = d * sc + pw;
        m = mn;
        acc[0] = acc[0]*sc + pw*v0.x;  acc[1] = acc[1]*sc + pw*v0.y;
        acc[2] = acc[2]*sc + pw*v0.z;  acc[3] = acc[3]*sc + pw*v0.w;
        acc[4] = acc[4]*sc + pw*v1.x;  acc[5] = acc[5]*sc + pw*v1.y;
        acc[6] = acc[6]*sc + pw*v1.z;  acc[7] = acc[7]*sc + pw*v1.w;
    }
    float inv = 1.f / (d + 1e-16f);
    float outv[8];
    #pragma unroll
    for (int i = 0; i < 8; i++) outv[i] = acc[i] * inv;

    // beta gate
    const float4* xp = (const float4*)(g_xr + (size_t)n * HC + off);
    float4 x0 = xp[0], x1 = xp[1];
    float xr[8] = {x0.x, x0.y, x0.z, x0.w, x1.x, x1.y, x1.z, x1.w};
    float bsum = 0.f;
    #pragma unroll
    for (int i = 0; i < 8; i++) {
        int idx = off + i;
        bsum += outv[i] * Wb[idx] + xr[i] * Wb[HC + idx] + (outv[i] - xr[i]) * Wb[2 * HC + idx];
    }
    float tot = breduce128(bsum, red);
    float beta = 1.f / (1.f + expf(-tot));

    float g[8], gsum = 0.f;
    #pragma unroll
    for (int i = 0; i < 8; i++) {
        g[i] = beta * xr[i] + (1.f - beta) * outv[i];
        gsum += g[i];
    }
    float mu = breduce128(gsum, red) * (1.f / HC);
    float vsum = 0.f;
    #pragma unroll
    for (int i = 0; i < 8; i++) { float dd = g[i] - mu; vsum += dd * dd; }
    float var = breduce128(vsum, red) * (1.f / HC);
    float rstd = rsqrtf(var + 1e-5f);

    const float4* lg = (const float4*)(lng + off);
    const float4* lb = (const float4*)(lnb + off);
    float4 lg0 = lg[0], lg1 = lg[1], lb0 = lb[0], lb1 = lb[1];
    float gl[8] = {lg0.x,lg0.y,lg0.z,lg0.w,lg1.x,lg1.y,lg1.z,lg1.w};
    float bl[8] = {lb0.x,lb0.y,lb0.z,lb0.w,lb1.x,lb1.y,lb1.z,lb1.w};
    float4 o0, o1;
    o0.x = (g[0]-mu)*rstd*gl[0]+bl[0]; o0.y = (g[1]-mu)*rstd*gl[1]+bl[1];
    o0.z = (g[2]-mu)*rstd*gl[2]+bl[2]; o0.w = (g[3]-mu)*rstd*gl[3]+bl[3];
    o1.x = (g[4]-mu)*rstd*gl[4]+bl[4]; o1.y = (g[5]-mu)*rstd*gl[5]+bl[5];
    o1.z = (g[6]-mu)*rstd*gl[6]+bl[6]; o1.w = (g[7]-mu)*rstd*gl[7]+bl[7];
    float4* op = (float4*)(g_out + (size_t)n * HC + off);
    op[0] = o0; op[1] = o1;
}

// ---------------- launch -----------------------------------------------------
extern "C" void kernel_launch(void* const* d_in, const int* in_sizes, int n_in,
                              void* d_out, int out_size) {
    const float* x    = (const float*)d_in[0];
    const int*   ei   = (const int*)  d_in[1];
    const float* Win  = (const float*)d_in[2];
    const float* b_in = (const float*)d_in[3];
    const float* Wq   = (const float*)d_in[4];
    const float* bq   = (const float*)d_in[5];
    const float* Wk   = (const float*)d_in[6];
    const float* bk   = (const float*)d_in[7];
    const float* Wv   = (const float*)d_in[8];
    const float* bv   = (const float*)d_in[9];
    const float* Ws   = (const float*)d_in[10];
    const float* bs   = (const float*)d_in[11];
    const float* Wb   = (const float*)d_in[12];
    const float* lng  = (const float*)d_in[13];
    const float* lnb  = (const float*)d_in[14];
    const float* Wp   = (const float*)d_in[15];
    const float* bp   = (const float*)d_in[16];
    float* out = (float*)d_out;

    float *g_h_p, *g_hn_p, *g_q_p, *g_k_p, *g_v_p, *g_xr_p, *g_out_p;
    cudaGetSymbolAddress((void**)&g_h_p,  g_h);
    cudaGetSymbolAddress((void**)&g_hn_p, g_hn);
    cudaGetSymbolAddress((void**)&g_q_p,  g_q);
    cudaGetSymbolAddress((void**)&g_k_p,  g_k);
    cudaGetSymbolAddress((void**)&g_v_p,  g_v);
    cudaGetSymbolAddress((void**)&g_xr_p, g_xr);
    cudaGetSymbolAddress((void**)&g_out_p, g_out);

    // CSR build (once per call; reused by all layers)
    csr_zero<<<(NN + 255) / 256, 256>>>();
    csr_count<<<(NE + 255) / 256, 256>>>(ei);
    csr_scan<<<1, 1024>>>();
    csr_fill<<<(NE + 255) / 256, 256>>>(ei);

    inproj_kernel<<<NN, 128>>>(x, Win, b_in, g_h_p);

    float* h  = g_h_p;
    float* hn = g_hn_p;
    dim3 grid_qkvs(32, (NN + 127) / 128);  // 32 x 157
    dim3 grid_proj(2,  (NN + 127) / 128);  //  2 x 157

    for (int l = 0; l < LAYERS; l++) {
        const float* wq = Wq + (size_t)l * HID * HC;
        const float* wk = Wk + (size_t)l * HID * HC;
        const float* wv = Wv + (size_t)l * HID * HC;
        const float* ws = Ws + (size_t)l * HID * HC;
        gemm_qkvs<<<grid_qkvs, 256>>>(h, wq, wk, wv, ws,
                                      bq + l * HC, bk + l * HC, bv + l * HC, bs + l * HC,
                                      g_q_p, g_k_p, g_v_p, g_xr_p, NN);

        attn_fused<<<NN, 128>>>(Wb + (size_t)l * 3 * HC,
                                lng + (size_t)l * HC, lnb + (size_t)l * HC);

        float* dst = (l == LAYERS - 1) ? out : hn;
        gemm_proj<<<grid_proj, 256>>>(g_out_p, Wp + (size_t)l * HC * HID,
                                      bp + (size_t)l * HID, h, dst, NN);
        if (l < LAYERS - 1) { float* t = h; h = hn; hn = t; }
    }
}

// round 5
// speedup vs baseline: 2.4992x; 1.5496x over previous
#include <cuda_runtime.h>
#include <cuda_bf16.h>
#include <math.h>
#include <stdint.h>

#define NN   20000
#define NE   160000
#define HID  128
#define HEADS 8
#define HC   1024
#define LAYERS 6

// ---------------- scratch (device globals; no allocation allowed) ----------
static __device__ float g_h  [NN * HID];
static __device__ float g_hn [NN * HID];
static __device__ float g_q  [NN * HC];
static __device__ float g_k  [NN * HC];
static __device__ float g_v  [NN * HC];
static __device__ float g_xr [NN * HC];
static __device__ float g_out[NN * HC];
// CSR
static __device__ int g_deg   [NN];
static __device__ int g_rowptr[NN + 1];
static __device__ int g_cur   [NN];
static __device__ int g_esrc  [NE];
// split-bf16 weights: qkvs transposed [z=l*4+ws][n=1024][k=128], proj [l][n=128][k=1024]
static __device__ __align__(16) __nv_bfloat16 g_wA_hi[LAYERS * 4 * 1024 * 128];
static __device__ __align__(16) __nv_bfloat16 g_wA_lo[LAYERS * 4 * 1024 * 128];
static __device__ __align__(16) __nv_bfloat16 g_wP_hi[LAYERS * 128 * 1024];
static __device__ __align__(16) __nv_bfloat16 g_wP_lo[LAYERS * 128 * 1024];

// ==================== mma.sync helpers =======================================
__device__ __forceinline__ uint32_t smem_u32(const void* p) {
    uint32_t a;
    asm("{ .reg .u64 t; cvta.to.shared.u64 t, %1; cvt.u32.u64 %0, t; }" : "=r"(a) : "l"(p));
    return a;
}
__device__ __forceinline__ void ldsm4(uint32_t& r0, uint32_t& r1, uint32_t& r2, uint32_t& r3,
                                      uint32_t addr) {
    asm volatile("ldmatrix.sync.aligned.m8n8.x4.shared.b16 {%0,%1,%2,%3}, [%4];"
                 : "=r"(r0), "=r"(r1), "=r"(r2), "=r"(r3) : "r"(addr));
}
__device__ __forceinline__ void mma16816(float* c, const uint32_t* a, uint32_t b0, uint32_t b1) {
    asm volatile("mma.sync.aligned.m16n8k16.row.col.f32.bf16.bf16.f32 "
                 "{%0,%1,%2,%3}, {%4,%5,%6,%7}, {%8,%9}, {%0,%1,%2,%3};"
                 : "+f"(c[0]), "+f"(c[1]), "+f"(c[2]), "+f"(c[3])
                 : "r"(a[0]), "r"(a[1]), "r"(a[2]), "r"(a[3]), "r"(b0), "r"(b1));
}
__device__ __forceinline__ uint32_t pack_bf2(__nv_bfloat16 x, __nv_bfloat16 y) {
    __nv_bfloat162 t(x, y);
    return *(uint32_t*)&t;
}
__device__ __forceinline__ void split2(float a, float b, uint32_t& hi, uint32_t& lo) {
    __nv_bfloat16 h0 = __float2bfloat16_rn(a), h1 = __float2bfloat16_rn(b);
    float l0 = a - __bfloat162float(h0), l1 = b - __bfloat162float(h1);
    hi = pack_bf2(h0, h1);
    lo = pack_bf2(__float2bfloat16_rn(l0), __float2bfloat16_rn(l1));
}
__device__ __forceinline__ void split8(float4 f0, float4 f1, uint4& h, uint4& l) {
    split2(f0.x, f0.y, h.x, l.x);
    split2(f0.z, f0.w, h.y, l.y);
    split2(f1.x, f1.y, h.z, l.z);
    split2(f1.z, f1.w, h.w, l.w);
}

// smem tile: [128 rows][256 bf16] = 512B/row = 32 chunks of 16B; hi = chunks 0-15, lo = 16-31
// swizzle: chunk' = chunk ^ (row & 7)  (lo offset = hi offset + 256 always)
__device__ __forceinline__ uint32_t sw_off(int r, int chunk) {
    return (uint32_t)(r * 512 + ((chunk ^ (r & 7)) << 4));
}

#define SA_OFF 0
#define SB_OFF 65536
#define MMASMEM 131072

// ---------------- MMA mainloop over one staged K=128 (8 k16 steps) ----------
__device__ __forceinline__ void mma_k128(uint32_t smA, uint32_t smB, int lane,
                                         int wm, int wn, float acc[2][8][4]) {
    int arow0 = wm * 32 + (lane & 15);
    int asel  = (lane >> 4) & 1;
    int brow0 = wn * 64 + (lane & 7) + ((lane >> 4) & 1) * 8;
    int bsel  = (lane >> 3) & 1;
    #pragma unroll
    for (int k16 = 0; k16 < 8; k16++) {
        int ch = 2 * k16;
        uint32_t ah[2][4], al[2][4];
        #pragma unroll
        for (int mf = 0; mf < 2; mf++) {
            int r = arow0 + mf * 16;
            uint32_t ad = smA + sw_off(r, ch + asel);
            ldsm4(ah[mf][0], ah[mf][1], ah[mf][2], ah[mf][3], ad);
            ldsm4(al[mf][0], al[mf][1], al[mf][2], al[mf][3], ad + 256);
        }
        uint32_t bh_[8][2], bl_[8][2];
        #pragma unroll
        for (int p = 0; p < 4; p++) {
            int r = brow0 + p * 16;
            uint32_t bd = smB + sw_off(r, ch + bsel);
            ldsm4(bh_[2*p][0], bh_[2*p][1], bh_[2*p+1][0], bh_[2*p+1][1], bd);
            ldsm4(bl_[2*p][0], bl_[2*p][1], bl_[2*p+1][0], bl_[2*p+1][1], bd + 256);
        }
        #pragma unroll
        for (int mf = 0; mf < 2; mf++)
            #pragma unroll
            for (int nf = 0; nf < 8; nf++) {
                mma16816(acc[mf][nf], ah[mf], bh_[nf][0], bh_[nf][1]);
                mma16816(acc[mf][nf], al[mf], bh_[nf][0], bh_[nf][1]);
                mma16816(acc[mf][nf], ah[mf], bl_[nf][0], bl_[nf][1]);
            }
    }
}

// ---------------- qkvs GEMM: C[ws] = h @ W[ws]^T(+b), M x 128-tile x 128-tile
// grid (32, 157): x = ws*8 + ntile, y = m-tile
__global__ __launch_bounds__(256, 1) void gemm_qkvs_mma(
        const float* __restrict__ A,
        const float* __restrict__ bq, const float* __restrict__ bk,
        const float* __restrict__ bv, const float* __restrict__ bs,
        int l, int M) {
    extern __shared__ char sm[];
    int tid = threadIdx.x, wid = tid >> 5, lane = tid & 31;
    int ws = blockIdx.x >> 3, ngrp = blockIdx.x & 7;
    int m0 = blockIdx.y * 128, n0 = ngrp * 128;
    int z = l * 4 + ws;
    const float* bias = ws == 0 ? bq : ws == 1 ? bk : ws == 2 ? bv : bs;
    float* C = ws == 0 ? g_q : ws == 1 ? g_k : ws == 2 ? g_v : g_xr;
    const uint4* bhp = (const uint4*)g_wA_hi + ((size_t)z * 1024 + n0) * 16;
    const uint4* blp = (const uint4*)g_wA_lo + ((size_t)z * 1024 + n0) * 16;

    // stage A (fp32 -> split bf16) and B (pre-split)
    for (int i = tid; i < 2048; i += 256) {
        int r = i >> 4, c = i & 15;
        uint32_t oh = sw_off(r, c);
        *(uint4*)(sm + SB_OFF + oh)       = bhp[r * 16 + c];
        *(uint4*)(sm + SB_OFF + oh + 256) = blp[r * 16 + c];
        int gm = m0 + r;
        float4 f0, f1;
        if (gm < M) {
            f0 = *(const float4*)(A + (size_t)gm * 128 + c * 8);
            f1 = *(const float4*)(A + (size_t)gm * 128 + c * 8 + 4);
        } else {
            f0 = make_float4(0.f, 0.f, 0.f, 0.f); f1 = f0;
        }
        uint4 h, lo;
        split8(f0, f1, h, lo);
        *(uint4*)(sm + SA_OFF + oh)       = h;
        *(uint4*)(sm + SA_OFF + oh + 256) = lo;
    }
    __syncthreads();

    float acc[2][8][4] = {};
    uint32_t smA = smem_u32(sm) + SA_OFF, smB = smem_u32(sm) + SB_OFF;
    int wm = wid >> 1, wn = wid & 1;
    mma_k128(smA, smB, lane, wm, wn, acc);

    // epilogue: + bias
    int colb = n0 + wn * 64 + (lane & 3) * 2;
    #pragma unroll
    for (int mf = 0; mf < 2; mf++) {
        int r0 = m0 + wm * 32 + mf * 16 + (lane >> 2);
        #pragma unroll
        for (int nf = 0; nf < 8; nf++) {
            int col = colb + nf * 8;
            float2 bb = *(const float2*)(bias + col);
            if (r0 < M) {
                float2 o = make_float2(acc[mf][nf][0] + bb.x, acc[mf][nf][1] + bb.y);
                *(float2*)(C + (size_t)r0 * HC + col) = o;
            }
            if (r0 + 8 < M) {
                float2 o = make_float2(acc[mf][nf][2] + bb.x, acc[mf][nf][3] + bb.y);
                *(float2*)(C + (size_t)(r0 + 8) * HC + col) = o;
            }
        }
    }
}

// ---------------- proj GEMM: C = relu(g_out @ Wp^T + bp + resid), N=128, K=1024
// grid (1, 157)
__global__ __launch_bounds__(256, 1) void gemm_proj_mma(
        const float* __restrict__ bias, const float* __restrict__ resid,
        float* __restrict__ C, int l, int M) {
    extern __shared__ char sm[];
    int tid = threadIdx.x, wid = tid >> 5, lane = tid & 31;
    int m0 = blockIdx.y * 128;
    const uint4* bhp = (const uint4*)g_wP_hi + (size_t)l * 128 * 128;  // [n=128][1024bf16 = 128 u4]
    const uint4* blp = (const uint4*)g_wP_lo + (size_t)l * 128 * 128;

    float acc[2][8][4] = {};
    uint32_t smA = smem_u32(sm) + SA_OFF, smB = smem_u32(sm) + SB_OFF;
    int wm = wid >> 1, wn = wid & 1;

    for (int ck = 0; ck < 8; ck++) {
        __syncthreads();
        for (int i = tid; i < 2048; i += 256) {
            int r = i >> 4, c = i & 15;
            uint32_t oh = sw_off(r, c);
            *(uint4*)(sm + SB_OFF + oh)       = bhp[r * 128 + ck * 16 + c];
            *(uint4*)(sm + SB_OFF + oh + 256) = blp[r * 128 + ck * 16 + c];
            int gm = m0 + r;
            float4 f0, f1;
            if (gm < M) {
                const float* ap = g_out + (size_t)gm * HC + ck * 128 + c * 8;
                f0 = *(const float4*)ap;
                f1 = *(const float4*)(ap + 4);
            } else {
                f0 = make_float4(0.f, 0.f, 0.f, 0.f); f1 = f0;
            }
            uint4 h, lo;
            split8(f0, f1, h, lo);
            *(uint4*)(sm + SA_OFF + oh)       = h;
            *(uint4*)(sm + SA_OFF + oh + 256) = lo;
        }
        __syncthreads();
        mma_k128(smA, smB, lane, wm, wn, acc);
    }

    int colb = wn * 64 + (lane & 3) * 2;
    #pragma unroll
    for (int mf = 0; mf < 2; mf++) {
        int r0 = m0 + wm * 32 + mf * 16 + (lane >> 2);
        #pragma unroll
        for (int nf = 0; nf < 8; nf++) {
            int col = colb + nf * 8;
            float2 bb = *(const float2*)(bias + col);
            if (r0 < M) {
                float2 rr = *(const float2*)(resid + (size_t)r0 * HID + col);
                float2 o;
                o.x = fmaxf(acc[mf][nf][0] + bb.x + rr.x, 0.f);
                o.y = fmaxf(acc[mf][nf][1] + bb.y + rr.y, 0.f);
                *(float2*)(C + (size_t)r0 * HID + col) = o;
            }
            if (r0 + 8 < M) {
                float2 rr = *(const float2*)(resid + (size_t)(r0 + 8) * HID + col);
                float2 o;
                o.x = fmaxf(acc[mf][nf][2] + bb.x + rr.x, 0.f);
                o.y = fmaxf(acc[mf][nf][3] + bb.y + rr.y, 0.f);
                *(float2*)(C + (size_t)(r0 + 8) * HID + col) = o;
            }
        }
    }
}

// ---------------- weight transpose + split ----------------------------------
// Wq/Wk/Wv/Ws: [LAYERS][128][1024] -> g_wA: [z=l*4+ws][n=1024][k=128] split hi/lo
__global__ void tsplit_qkvs(const float* __restrict__ Wq, const float* __restrict__ Wk,
                            const float* __restrict__ Wv, const float* __restrict__ Ws) {
    __shared__ float t[32][33];
    int z = blockIdx.z, l = z >> 2, ws = z & 3;
    const float* W = (ws == 0 ? Wq : ws == 1 ? Wk : ws == 2 ? Wv : Ws) + (size_t)l * 128 * HC;
    __nv_bfloat16* oh = g_wA_hi + (size_t)z * 1024 * 128;
    __nv_bfloat16* ol = g_wA_lo + (size_t)z * 1024 * 128;
    int n0 = blockIdx.x * 32, k0 = blockIdx.y * 32;
    int tx = threadIdx.x, ty = threadIdx.y;
    #pragma unroll
    for (int i = 0; i < 4; i++)
        t[ty + 8 * i][tx] = W[(size_t)(k0 + ty + 8 * i) * HC + n0 + tx];
    __syncthreads();
    #pragma unroll
    for (int i = 0; i < 4; i++) {
        float v = t[tx][ty + 8 * i];
        __nv_bfloat16 h = __float2bfloat16_rn(v);
        size_t o = (size_t)(n0 + ty + 8 * i) * 128 + k0 + tx;
        oh[o] = h;
        ol[o] = __float2bfloat16_rn(v - __bfloat162float(h));
    }
}
// Wp: [LAYERS][1024][128] -> g_wP: [l][n=128][k=1024] split hi/lo
__global__ void tsplit_proj(const float* __restrict__ Wp) {
    __shared__ float t[32][33];
    int l = blockIdx.z;
    const float* W = Wp + (size_t)l * 1024 * 128;
    __nv_bfloat16* oh = g_wP_hi + (size_t)l * 128 * 1024;
    __nv_bfloat16* ol = g_wP_lo + (size_t)l * 128 * 1024;
    int n0 = blockIdx.x * 32, k0 = blockIdx.y * 32;
    int tx = threadIdx.x, ty = threadIdx.y;
    #pragma unroll
    for (int i = 0; i < 4; i++)
        t[ty + 8 * i][tx] = W[(size_t)(k0 + ty + 8 * i) * 128 + n0 + tx];
    __syncthreads();
    #pragma unroll
    for (int i = 0; i < 4; i++) {
        float v = t[tx][ty + 8 * i];
        __nv_bfloat16 h = __float2bfloat16_rn(v);
        size_t o = (size_t)(n0 + ty + 8 * i) * 1024 + k0 + tx;
        oh[o] = h;
        ol[o] = __float2bfloat16_rn(v - __bfloat162float(h));
    }
}

// ---------------- input projection ------------------------------------------
__global__ void inproj_kernel(const float* __restrict__ x,
                              const float* __restrict__ Win,
                              const float* __restrict__ b_in,
                              float* __restrict__ h) {
    int n = blockIdx.x;
    int j = threadIdx.x;
    __shared__ float sx[15];
    if (j < 15) sx[j] = x[n * 15 + j];
    __syncthreads();
    float acc = b_in[j];
    #pragma unroll
    for (int k = 0; k < 15; k++) acc += sx[k] * Win[k * HID + j];
    h[n * HID + j] = acc;
}

// ---------------- CSR build --------------------------------------------------
__global__ void csr_zero() {
    int i = blockIdx.x * blockDim.x + threadIdx.x;
    if (i < NN) g_deg[i] = 0;
}
__global__ void csr_count(const int* __restrict__ ei) {
    int e = blockIdx.x * blockDim.x + threadIdx.x;
    if (e < NE) atomicAdd(&g_deg[ei[NE + e]], 1);
}
__global__ __launch_bounds__(1024) void csr_scan() {
    __shared__ int wsum[32], wofs[32], s_tot;
    int t = threadIdx.x, lane = t & 31, w = t >> 5;
    int base = 0;
    for (int i0 = 0; i0 < NN; i0 += 1024) {
        int i = i0 + t;
        int v = (i < NN) ? g_deg[i] : 0;
        int s = v;
        #pragma unroll
        for (int o = 1; o < 32; o <<= 1) {
            int u = __shfl_up_sync(0xffffffffu, s, o);
            if (lane >= o) s += u;
        }
        if (lane == 31) wsum[w] = s;
        __syncthreads();
        if (w == 0) {
            int a = wsum[lane];
            int ss = a;
            #pragma unroll
            for (int o = 1; o < 32; o <<= 1) {
                int u = __shfl_up_sync(0xffffffffu, ss, o);
                if (lane >= o) ss += u;
            }
            wofs[lane] = ss - a;
            if (lane == 31) s_tot = ss;
        }
        __syncthreads();
        int excl = base + wofs[w] + (s - v);
        if (i < NN) { g_rowptr[i] = excl; g_cur[i] = excl; }
        base += s_tot;
        __syncthreads();
    }
    if (t == 0) g_rowptr[NN] = base;
}
__global__ void csr_fill(const int* __restrict__ ei) {
    int e = blockIdx.x * blockDim.x + threadIdx.x;
    if (e < NE) {
        int dst = ei[NE + e];
        int pos = atomicAdd(&g_cur[dst], 1);
        g_esrc[pos] = ei[e];
    }
}

// ---------------- fused attention + beta gate + LayerNorm -------------------
__device__ __forceinline__ float breduce128(float v, float* red) {
    #pragma unroll
    for (int o = 16; o; o >>= 1) v += __shfl_xor_sync(0xffffffffu, v, o);
    if ((threadIdx.x & 31) == 0) red[threadIdx.x >> 5] = v;
    __syncthreads();
    float r = red[0] + red[1] + red[2] + red[3];
    __syncthreads();
    return r;
}

__global__ __launch_bounds__(128) void attn_fused(
        const float* __restrict__ Wb, const float* __restrict__ lng,
        const float* __restrict__ lnb) {
    int n = blockIdx.x;
    int t = threadIdx.x;
    int off = (t >> 4) * 128 + (t & 15) * 8;
    __shared__ float red[4];

    const float4* qp = (const float4*)(g_q + (size_t)n * HC + off);
    float4 q0 = qp[0], q1 = qp[1];

    float acc[8] = {0.f, 0.f, 0.f, 0.f, 0.f, 0.f, 0.f, 0.f};
    float m = __int_as_float(0xff800000);
    float d = 0.f;

    int beg = g_rowptr[n], end = g_rowptr[n + 1];
    for (int p = beg; p < end; p++) {
        int src = g_esrc[p];
        const float4* kp = (const float4*)(g_k + (size_t)src * HC + off);
        const float4* vp = (const float4*)(g_v + (size_t)src * HC + off);
        float4 k0 = kp[0], k1 = kp[1];
        float4 v0 = vp[0], v1 = vp[1];
        float dot = q0.x*k0.x + q0.y*k0.y + q0.z*k0.z + q0.w*k0.w
                  + q1.x*k1.x + q1.y*k1.y + q1.z*k1.z + q1.w*k1.w;
        #pragma unroll
        for (int o = 8; o; o >>= 1) dot += __shfl_xor_sync(0xffffffffu, dot, o);
        float alpha = dot * 0.08838834764831845f;
        float mn = fmaxf(m, alpha);
        float sc = expf(m - mn);
        float pw = expf(alpha - mn);
        d = d * sc + pw;
        m = mn;
        acc[0] = acc[0]*sc + pw*v0.x;  acc[1] = acc[1]*sc + pw*v0.y;
        acc[2] = acc[2]*sc + pw*v0.z;  acc[3] = acc[3]*sc + pw*v0.w;
        acc[4] = acc[4]*sc + pw*v1.x;  acc[5] = acc[5]*sc + pw*v1.y;
        acc[6] = acc[6]*sc + pw*v1.z;  acc[7] = acc[7]*sc + pw*v1.w;
    }
    float inv = 1.f / (d + 1e-16f);
    float outv[8];
    #pragma unroll
    for (int i = 0; i < 8; i++) outv[i] = acc[i] * inv;

    const float4* xp = (const float4*)(g_xr + (size_t)n * HC + off);
    float4 x0 = xp[0], x1 = xp[1];
    float xr[8] = {x0.x, x0.y, x0.z, x0.w, x1.x, x1.y, x1.z, x1.w};
    float bsum = 0.f;
    #pragma unroll
    for (int i = 0; i < 8; i++) {
        int idx = off + i;
        bsum += outv[i] * Wb[idx] + xr[i] * Wb[HC + idx] + (outv[i] - xr[i]) * Wb[2 * HC + idx];
    }
    float tot = breduce128(bsum, red);
    float beta = 1.f / (1.f + expf(-tot));

    float g[8], gsum = 0.f;
    #pragma unroll
    for (int i = 0; i < 8; i++) {
        g[i] = beta * xr[i] + (1.f - beta) * outv[i];
        gsum += g[i];
    }
    float mu = breduce128(gsum, red) * (1.f / HC);
    float vsum = 0.f;
    #pragma unroll
    for (int i = 0; i < 8; i++) { float dd = g[i] - mu; vsum += dd * dd; }
    float var = breduce128(vsum, red) * (1.f / HC);
    float rstd = rsqrtf(var + 1e-5f);

    const float4* lg = (const float4*)(lng + off);
    const float4* lb = (const float4*)(lnb + off);
    float4 lg0 = lg[0], lg1 = lg[1], lb0 = lb[0], lb1 = lb[1];
    float gl[8] = {lg0.x, lg0.y, lg0.z, lg0.w, lg1.x, lg1.y, lg1.z, lg1.w};
    float bl[8] = {lb0.x, lb0.y, lb0.z, lb0.w, lb1.x, lb1.y, lb1.z, lb1.w};
    float4 o0, o1;
    o0.x = (g[0]-mu)*rstd*gl[0]+bl[0]; o0.y = (g[1]-mu)*rstd*gl[1]+bl[1];
    o0.z = (g[2]-mu)*rstd*gl[2]+bl[2]; o0.w = (g[3]-mu)*rstd*gl[3]+bl[3];
    o1.x = (g[4]-mu)*rstd*gl[4]+bl[4]; o1.y = (g[5]-mu)*rstd*gl[5]+bl[5];
    o1.z = (g[6]-mu)*rstd*gl[6]+bl[6]; o1.w = (g[7]-mu)*rstd*gl[7]+bl[7];
    float4* op = (float4*)(g_out + (size_t)n * HC + off);
    op[0] = o0; op[1] = o1;
}

// ---------------- launch -----------------------------------------------------
extern "C" void kernel_launch(void* const* d_in, const int* in_sizes, int n_in,
                              void* d_out, int out_size) {
    const float* x    = (const float*)d_in[0];
    const int*   ei   = (const int*)  d_in[1];
    const float* Win  = (const float*)d_in[2];
    const float* b_in = (const float*)d_in[3];
    const float* Wq   = (const float*)d_in[4];
    const float* bq   = (const float*)d_in[5];
    const float* Wk   = (const float*)d_in[6];
    const float* bk   = (const float*)d_in[7];
    const float* Wv   = (const float*)d_in[8];
    const float* bv   = (const float*)d_in[9];
    const float* Ws   = (const float*)d_in[10];
    const float* bs   = (const float*)d_in[11];
    const float* Wb   = (const float*)d_in[12];
    const float* lng  = (const float*)d_in[13];
    const float* lnb  = (const float*)d_in[14];
    const float* Wp   = (const float*)d_in[15];
    const float* bp   = (const float*)d_in[16];
    float* out = (float*)d_out;

    float *g_h_p, *g_hn_p;
    cudaGetSymbolAddress((void**)&g_h_p,  g_h);
    cudaGetSymbolAddress((void**)&g_hn_p, g_hn);

    cudaFuncSetAttribute(gemm_qkvs_mma, cudaFuncAttributeMaxDynamicSharedMemorySize, MMASMEM);
    cudaFuncSetAttribute(gemm_proj_mma, cudaFuncAttributeMaxDynamicSharedMemorySize, MMASMEM);

    // CSR build + weight split (once per call)
    csr_zero<<<(NN + 255) / 256, 256>>>();
    csr_count<<<(NE + 255) / 256, 256>>>(ei);
    csr_scan<<<1, 1024>>>();
    csr_fill<<<(NE + 255) / 256, 256>>>(ei);
    tsplit_qkvs<<<dim3(32, 4, LAYERS * 4), dim3(32, 8)>>>(Wq, Wk, Wv, Ws);
    tsplit_proj<<<dim3(4, 32, LAYERS), dim3(32, 8)>>>(Wp);

    inproj_kernel<<<NN, 128>>>(x, Win, b_in, g_h_p);

    float* h  = g_h_p;
    float* hn = g_hn_p;
    int mtiles = (NN + 127) / 128;   // 157

    for (int l = 0; l < LAYERS; l++) {
        gemm_qkvs_mma<<<dim3(32, mtiles), 256, MMASMEM>>>(
            h, bq + l * HC, bk + l * HC, bv + l * HC, bs + l * HC, l, NN);

        attn_fused<<<NN, 128>>>(Wb + (size_t)l * 3 * HC,
                                lng + (size_t)l * HC, lnb + (size_t)l * HC);

        float* dst = (l == LAYERS - 1) ? out : hn;
        gemm_proj_mma<<<dim3(1, mtiles), 256, MMASMEM>>>(
            bp + (size_t)l * HID, h, dst, l, NN);
        if (l < LAYERS - 1) { float* t = h; h = hn; hn = t; }
    }
}